// round 15
// baseline (speedup 1.0000x reference)
#include <cuda_runtime.h>
#include <cuda_bf16.h>
#include <stdint.h>
#include <math.h>

// Problem constants (B=8, N=1025, D=64)
#define Nn     1025
#define Dd     64
#define Tt     8192      // B*(N-1)
#define MASKN  8200      // B*N

#define BM     128
#define BN     128
#define SPLITS 8
#define NBLK_B 256                  // gemm grid; item loop covers (rowtile,split)
#define NBLKP  256                  // prep blocks (32 rows each)

#define SCALE_Q 28.85390081777927f   // log2(e)/0.05
#define C0x    (-28.85390081777927f) // -20*log2(e)
#define LN2f    0.6931471805599453f

// Device scratch (zero-initialized at module load; rows >= count stay 0)
__device__ int   g_count;
__device__ int   g_arr;     // prep arrival counter; reset by gemm each replay
__device__ int   g_done2;   // gemm arrival counter; reset by prep each replay
__device__ int   g_blkcnt[NBLKP];
__device__ __align__(16) __nv_bfloat16 g_qh[Tt * Dd];
__device__ __align__(16) __nv_bfloat16 g_kh[Tt * Dd];
__device__ float g_diag[Tt];
__device__ __align__(32) float g_S2[Tt * SPLITS];   // [row][split]

// ---------------------------------------------------------------------------
// PTX helpers
// ---------------------------------------------------------------------------
__device__ __forceinline__ float ex2(float x) {
    float r; asm("ex2.approx.f32 %0, %1;" : "=f"(r) : "f"(x)); return r;
}
__device__ __forceinline__ float lg2(float x) {
    float r; asm("lg2.approx.f32 %0, %1;" : "=f"(r) : "f"(x)); return r;
}
__device__ __forceinline__ void ldsm4(uint32_t r[4], uint32_t addr) {
    asm volatile("ldmatrix.sync.aligned.m8n8.x4.shared.b16 {%0,%1,%2,%3}, [%4];"
        : "=r"(r[0]), "=r"(r[1]), "=r"(r[2]), "=r"(r[3]) : "r"(addr));
}
__device__ __forceinline__ void mma16816(float d[4], const uint32_t a[4],
                                         uint32_t b0, uint32_t b1) {
    asm volatile(
        "mma.sync.aligned.m16n8k16.row.col.f32.bf16.bf16.f32 "
        "{%0,%1,%2,%3},{%4,%5,%6,%7},{%8,%9},{%0,%1,%2,%3};"
        : "+f"(d[0]), "+f"(d[1]), "+f"(d[2]), "+f"(d[3])
        : "r"(a[0]), "r"(a[1]), "r"(a[2]), "r"(a[3]), "r"(b0), "r"(b1));
}
__device__ __forceinline__ void cpa16(uint32_t dst, const void* src) {
    asm volatile("cp.async.cg.shared.global [%0], [%1], 16;" :: "r"(dst), "l"(src));
}
__device__ __forceinline__ void cpa_commit() {
    asm volatile("cp.async.commit_group;" ::: "memory");
}
template<int N> __device__ __forceinline__ void cpa_wait() {
    asm volatile("cp.async.wait_group %0;" :: "n"(N) : "memory");
}

// nz-pattern contribution of 4 bytes: byte j -> bit j
__device__ __forceinline__ int nz4(uint32_t w) {
    int p = 0;
    if (w & 0x000000FFu) p |= 1;
    if (w & 0x0000FF00u) p |= 2;
    if (w & 0x00FF0000u) p |= 4;
    if (w & 0xFF000000u) p |= 8;
    return p;
}

// ---------------------------------------------------------------------------
// Kernel 1 (fused scan+prep): 256 blocks x 1024 threads, 32 rows/block.
// Distributed scan; all blocks co-resident (launch_bounds 1024,2).
// ---------------------------------------------------------------------------
__global__ __launch_bounds__(1024, 2) void prep_kernel(const float* __restrict__ qemb,
                                                       const float* __restrict__ kemb,
                                                       const uint8_t* __restrict__ maskraw) {
    __shared__ int s_nz;
    __shared__ unsigned s_bits;
    __shared__ int s_base, s_total;
    int tid = threadIdx.x, lane = tid & 31, warp = tid >> 5;
    int bid = blockIdx.x;
    int br0 = bid * 32;

    if (tid == 0) s_nz = 0;
    if (bid == 0 && tid == 512) g_done2 = 0;   // reset gemm counter this replay
    __syncthreads();

    // --- dtype sniff: one uint2 load/thread over the byte region ---
    const uint2* mv = (const uint2*)maskraw;
    uint2 v = mv[tid];
    int local = nz4(v.x) | nz4(v.y);
    if (tid == 1023) {                         // tail bytes 8192..8199
        uint2 t = mv[1024];
        local |= nz4(t.x) | nz4(t.y);
    }
#pragma unroll
    for (int o = 16; o; o >>= 1) local |= __shfl_xor_sync(0xffffffffu, local, o);
    if (lane == 0 && local) atomicOr(&s_nz, local);
    __syncthreads();

    int nz = s_nz;
    int mode;                       // 0=uint8, 1=int32, 2=float32
    if ((nz & 0xE) == 0)       mode = 1;
    else if ((nz & 0x3) == 0)  mode = 2;
    else                       mode = 0;

    // --- phase A: this block's 32 valid flags (warp 0), publish count ---
    if (warp == 0) {
        int row = br0 + lane;
        int b = row >> 10, r = row & 1023;
        int mi = b * Nn + r + 1;
        int vv;
        if (mode == 1)      vv = ((const int*)maskraw)[mi] != 0;
        else if (mode == 2) vv = ((const float*)maskraw)[mi] != 0.0f;
        else                vv = maskraw[mi] != 0;
        unsigned bits = __ballot_sync(0xffffffffu, vv);
        if (lane == 0) {
            s_bits = bits;
            g_blkcnt[bid] = __popc(bits);
            __threadfence();
            atomicAdd(&g_arr, 1);
        }
    }

    // --- wait for all 256 block counts (short: phase A is parallel) ---
    if (tid == 0) {
        while (atomicAdd(&g_arr, 0) < NBLKP) __nanosleep(32);
    }
    __syncthreads();
    __threadfence();

    // --- exclusive base + total over 256 counts (warp 0) ---
    if (warp == 0) {
        int t = 0, s = 0;
#pragma unroll
        for (int j = 0; j < 8; j++) {
            int idx = lane * 8 + j;
            int cc = g_blkcnt[idx];
            t += cc;
            if (idx < bid) s += cc;
        }
#pragma unroll
        for (int o = 16; o; o >>= 1) {
            t += __shfl_xor_sync(0xffffffffu, t, o);
            s += __shfl_xor_sync(0xffffffffu, s, o);
        }
        if (lane == 0) { s_base = s; s_total = t; }
    }
    __syncthreads();

    if (bid == 0 && tid == 0) g_count = s_total;

    // --- phase B: gather. one warp per row ---
    unsigned bits = s_bits;
    if (!((bits >> warp) & 1u)) return;
    int pos = s_base + __popc(bits & ((1u << warp) - 1u));
    int row = br0 + warp;
    int b = row >> 10, r = row & 1023;
    float2 qv = ((const float2*)(qemb + (size_t)(b * Nn + r) * Dd))[lane];
    float2 kv = ((const float2*)(kemb + (size_t)(b * Nn + r + 1) * Dd))[lane];
    float qs = fmaf(qv.x, qv.x, qv.y * qv.y);
    float ks = fmaf(kv.x, kv.x, kv.y * kv.y);
#pragma unroll
    for (int o = 16; o; o >>= 1) {
        qs += __shfl_xor_sync(0xffffffffu, qs, o);
        ks += __shfl_xor_sync(0xffffffffu, ks, o);
    }
    float qn = SCALE_Q / fmaxf(sqrtf(qs), 1e-12f);
    float kn = 1.0f    / fmaxf(sqrtf(ks), 1e-12f);
    __nv_bfloat162 qb = __floats2bfloat162_rn(qv.x * qn, qv.y * qn);
    __nv_bfloat162 kb = __floats2bfloat162_rn(kv.x * kn, kv.y * kn);
    ((__nv_bfloat162*)(g_qh + (size_t)pos * Dd))[lane] = qb;
    ((__nv_bfloat162*)(g_kh + (size_t)pos * Dd))[lane] = kb;
    float d = fmaf(__bfloat162float(qb.x), __bfloat162float(kb.x),
                   __bfloat162float(qb.y) * __bfloat162float(kb.y));
#pragma unroll
    for (int o = 16; o; o >>= 1) d += __shfl_xor_sync(0xffffffffu, d, o);
    if (lane == 0) g_diag[pos] = d;
}

// ---------------------------------------------------------------------------
// Kernel 2: 128x128 bf16 tensor-core GEMM + fused exp2 (f32 MUFU) row-sum.
// grid = 256 blocks; items (row-tile, split) looped -> no dead blocks.
// cp.async double-buffered B pipeline; last-arriving block does final reduce.
// ---------------------------------------------------------------------------
__global__ __launch_bounds__(256, 2) void gemm_kernel(float* __restrict__ out) {
    __shared__ __align__(16) uint4 As[BM * 8];      // 16 KB (reused post-afrag)
    __shared__ __align__(16) uint4 Bs[2][BN * 8];   // 32 KB double buffer

    float* ssum    = (float*)As;                    // [2][BM] = 1 KB overlay
    int*   amLastp = (int*)((char*)As + 1024);
    float* sblk    = (float*)((char*)As + 1088);    // 8 floats

    int count = g_count;
    int tid   = threadIdx.x;
    int lane  = tid & 31;
    int wid   = tid >> 5;
    int wm    = wid & 3;      // 0..3 : rows wm*32
    int wn    = wid >> 2;     // 0..1 : cols wn*64

    uint32_t asb = (uint32_t)__cvta_generic_to_shared(As);
    uint32_t bsb = (uint32_t)__cvta_generic_to_shared(Bs);
    int ntiles = (count + BN - 1) >> 7;
    int nitems = ntiles * SPLITS;

    for (int item = blockIdx.x; item < nitems; item += NBLK_B) {
        int row0  = (item >> 3) * BM;
        int split = item & 7;
        if (row0 >= count) continue;

        // issue A tile (cp.async, swizzled)
        {
            const char* src = (const char*)(g_qh + (size_t)row0 * Dd);
#pragma unroll
            for (int i = 0; i < 4; i++) {
                int c = tid + i * 256;
                int r = c >> 3, k16 = c & 7;
                cpa16(asb + (uint32_t)((r * 8 + (k16 ^ (r & 7))) * 16), src + (size_t)c * 16);
            }
        }
        cpa_commit();                       // group: A
        // first B tile into buf 0
        {
            const char* src = (const char*)(g_kh + ((size_t)split << 7) * Dd);
#pragma unroll
            for (int i = 0; i < 4; i++) {
                int c = tid + i * 256;
                int r = c >> 3, k16 = c & 7;
                cpa16(bsb + (uint32_t)((r * 8 + (k16 ^ (r & 7))) * 16), src + (size_t)c * 16);
            }
        }
        cpa_commit();                       // group: B0
        cpa_wait<1>();                      // A retired (B0 may be in flight)
        __syncthreads();

        // Hoist all A fragments (rows wm*32..+32, full K=64)
        uint32_t afrag[2][4][4];
#pragma unroll
        for (int mi = 0; mi < 2; mi++)
#pragma unroll
            for (int ks = 0; ks < 4; ks++) {
                int m = lane >> 3;
                int r = wm * 32 + mi * 16 + ((m & 1) << 3) + (lane & 7);
                int c = 2 * ks + (m >> 1);
                ldsm4(afrag[mi][ks], asb + (uint32_t)(r * 8 + (c ^ (r & 7))) * 16);
            }
        __syncthreads();                    // As dead -> overlay safe

        float rsum[4] = {0.f, 0.f, 0.f, 0.f};
        int ct = split, buf = 0;

        while (ct < ntiles) {
            cpa_wait<0>();                  // B(ct) resident in Bs[buf]
            __syncthreads();
            int ctn = ct + SPLITS;
            if (ctn < ntiles) {             // prefetch next into other buffer
                const char* src = (const char*)(g_kh + ((size_t)ctn << 7) * Dd);
                uint32_t base = bsb + (buf ^ 1) * 16384;
#pragma unroll
                for (int i = 0; i < 4; i++) {
                    int c = tid + i * 256;
                    int r = c >> 3, k16 = c & 7;
                    cpa16(base + (uint32_t)((r * 8 + (k16 ^ (r & 7))) * 16), src + (size_t)c * 16);
                }
            }
            cpa_commit();

            int col0 = ct << 7;
            bool full = (col0 + BN) <= count;
            uint32_t bb = bsb + buf * 16384;

#pragma unroll
            for (int nh = 0; nh < 2; nh++) {
                float acc[2][4][4];
#pragma unroll
                for (int mi = 0; mi < 2; mi++)
#pragma unroll
                    for (int ni = 0; ni < 4; ni++)
#pragma unroll
                        for (int j = 0; j < 4; j++) acc[mi][ni][j] = C0x;

#pragma unroll
                for (int ks = 0; ks < 4; ks++) {
                    uint32_t bfr[2][4];
#pragma unroll
                    for (int p = 0; p < 2; p++) {
                        int ni0 = nh * 4 + p * 2;
                        int m = lane >> 3;
                        int r = wn * 64 + ni0 * 8 + ((m >> 1) << 3) + (lane & 7);
                        int c = 2 * ks + (m & 1);
                        ldsm4(bfr[p], bb + (uint32_t)(r * 8 + (c ^ (r & 7))) * 16);
                    }
#pragma unroll
                    for (int mi = 0; mi < 2; mi++) {
                        mma16816(acc[mi][0], afrag[mi][ks], bfr[0][0], bfr[0][1]);
                        mma16816(acc[mi][1], afrag[mi][ks], bfr[0][2], bfr[0][3]);
                        mma16816(acc[mi][2], afrag[mi][ks], bfr[1][0], bfr[1][1]);
                        mma16816(acc[mi][3], afrag[mi][ks], bfr[1][2], bfr[1][3]);
                    }
                }

                if (full) {
#pragma unroll
                    for (int mi = 0; mi < 2; mi++)
#pragma unroll
                        for (int ni = 0; ni < 4; ni++) {
                            rsum[mi * 2 + 0] += ex2(acc[mi][ni][0]) + ex2(acc[mi][ni][1]);
                            rsum[mi * 2 + 1] += ex2(acc[mi][ni][2]) + ex2(acc[mi][ni][3]);
                        }
                } else {
                    int cb = col0 + wn * 64 + nh * 32 + (lane & 3) * 2;
#pragma unroll
                    for (int mi = 0; mi < 2; mi++)
#pragma unroll
                        for (int ni = 0; ni < 4; ni++) {
                            int c0 = cb + ni * 8;
                            float e0 = (c0     < count) ? ex2(acc[mi][ni][0]) : 0.f;
                            float e1 = (c0 + 1 < count) ? ex2(acc[mi][ni][1]) : 0.f;
                            float e2 = (c0     < count) ? ex2(acc[mi][ni][2]) : 0.f;
                            float e3 = (c0 + 1 < count) ? ex2(acc[mi][ni][3]) : 0.f;
                            rsum[mi * 2 + 0] += e0 + e1;
                            rsum[mi * 2 + 1] += e2 + e3;
                        }
                }
            }
            ct = ctn; buf ^= 1;
        }

        // lanes sharing a row: l%4 (column quads)
#pragma unroll
        for (int i = 0; i < 4; i++) {
            rsum[i] += __shfl_xor_sync(0xffffffffu, rsum[i], 1);
            rsum[i] += __shfl_xor_sync(0xffffffffu, rsum[i], 2);
        }
        __syncthreads();                 // overlay region free
        if ((lane & 3) == 0) {
#pragma unroll
            for (int i = 0; i < 4; i++) {
                int row = wm * 32 + (i >> 1) * 16 + (i & 1) * 8 + (lane >> 2);
                ssum[wn * BM + row] = rsum[i];
            }
        }
        __syncthreads();
        if (tid < BM)
            g_S2[(size_t)(row0 + tid) * SPLITS + split] = ssum[tid] + ssum[BM + tid];
        __syncthreads();                 // ssum consumed before next item's A load
    }

    // ---- fused final reduce: last-arriving block does it all ----
    __threadfence();            // order this thread's global stores
    __syncthreads();            // all threads' fences done before tid0 arrives
    if (tid == 0)
        *amLastp = (atomicAdd(&g_done2, 1) == NBLK_B - 1) ? 1 : 0;
    __syncthreads();
    if (!*amLastp) return;
    __threadfence();            // acquire: make all blocks' stores visible

    if (tid == 0) g_arr = 0;    // reset prep arrival counter for next replay

    float acc = 0.f;
    for (int r = tid; r < count; r += 256) {
        float4 a = *(const float4*)&g_S2[(size_t)r * SPLITS];
        float4 b = *(const float4*)&g_S2[(size_t)r * SPLITS + 4];
        float S = ((a.x + a.y) + (a.z + a.w)) + ((b.x + b.y) + (b.z + b.w));
        acc += g_diag[r] + C0x - lg2(S);
    }
#pragma unroll
    for (int o = 16; o; o >>= 1) acc += __shfl_xor_sync(0xffffffffu, acc, o);
    if (lane == 0) sblk[wid] = acc;
    __syncthreads();
    if (tid == 0) {
        float s = 0.f;
#pragma unroll
        for (int w = 0; w < 8; w++) s += sblk[w];
        out[0] = -LN2f * s / (float)count;
    }
}

// ---------------------------------------------------------------------------
extern "C" void kernel_launch(void* const* d_in, const int* in_sizes, int n_in,
                              void* d_out, int out_size) {
    const float*   q = (const float*)d_in[0];
    const float*   k = (const float*)d_in[1];
    const uint8_t* m = (const uint8_t*)d_in[2];
    (void)in_sizes; (void)n_in; (void)out_size;

    prep_kernel<<<NBLKP, 1024>>>(q, k, m);
    gemm_kernel<<<NBLK_B, 256>>>((float*)d_out);
}

// round 16
// speedup vs baseline: 1.0089x; 1.0089x over previous
#include <cuda_runtime.h>
#include <cuda_bf16.h>
#include <stdint.h>
#include <math.h>

// Problem constants (B=8, N=1025, D=64)
#define Nn     1025
#define Dd     64
#define Tt     8192      // B*(N-1)
#define MASKN  8200      // B*N

#define BM     128
#define BN     128
#define SPLITS 16
#define NBLK_B 512                  // gemm grid; item loop covers (rowtile,split)
#define NBLKP  256                  // prep blocks (32 rows each)

#define SCALE_Q 28.85390081777927f   // log2(e)/0.05
#define C0x    (-28.85390081777927f) // -20*log2(e)
#define LN2f    0.6931471805599453f

// Device scratch (zero-initialized at module load; rows >= count stay 0)
__device__ int   g_count;
__device__ int   g_arr;     // prep arrival counter; reset by gemm each replay
__device__ int   g_done2;   // gemm arrival counter; reset by prep each replay
__device__ int   g_blkcnt[NBLKP];
__device__ __align__(16) __nv_bfloat16 g_qh[Tt * Dd];
__device__ __align__(16) __nv_bfloat16 g_kh[Tt * Dd];
__device__ float g_diag[Tt];
__device__ __align__(64) float g_S2[Tt * SPLITS];   // [row][split]

// ---------------------------------------------------------------------------
// PTX helpers
// ---------------------------------------------------------------------------
__device__ __forceinline__ float ex2(float x) {
    float r; asm("ex2.approx.f32 %0, %1;" : "=f"(r) : "f"(x)); return r;
}
__device__ __forceinline__ float lg2(float x) {
    float r; asm("lg2.approx.f32 %0, %1;" : "=f"(r) : "f"(x)); return r;
}
__device__ __forceinline__ void ldsm4(uint32_t r[4], uint32_t addr) {
    asm volatile("ldmatrix.sync.aligned.m8n8.x4.shared.b16 {%0,%1,%2,%3}, [%4];"
        : "=r"(r[0]), "=r"(r[1]), "=r"(r[2]), "=r"(r[3]) : "r"(addr));
}
__device__ __forceinline__ void mma16816(float d[4], const uint32_t a[4],
                                         uint32_t b0, uint32_t b1) {
    asm volatile(
        "mma.sync.aligned.m16n8k16.row.col.f32.bf16.bf16.f32 "
        "{%0,%1,%2,%3},{%4,%5,%6,%7},{%8,%9},{%0,%1,%2,%3};"
        : "+f"(d[0]), "+f"(d[1]), "+f"(d[2]), "+f"(d[3])
        : "r"(a[0]), "r"(a[1]), "r"(a[2]), "r"(a[3]), "r"(b0), "r"(b1));
}
__device__ __forceinline__ void cpa16(uint32_t dst, const void* src) {
    asm volatile("cp.async.cg.shared.global [%0], [%1], 16;" :: "r"(dst), "l"(src));
}
__device__ __forceinline__ void cpa_commit() {
    asm volatile("cp.async.commit_group;" ::: "memory");
}
template<int N> __device__ __forceinline__ void cpa_wait() {
    asm volatile("cp.async.wait_group %0;" :: "n"(N) : "memory");
}

// nz-pattern contribution of 4 bytes: byte j -> bit j
__device__ __forceinline__ int nz4(uint32_t w) {
    int p = 0;
    if (w & 0x000000FFu) p |= 1;
    if (w & 0x0000FF00u) p |= 2;
    if (w & 0x00FF0000u) p |= 4;
    if (w & 0xFF000000u) p |= 8;
    return p;
}

// ---------------------------------------------------------------------------
// Kernel 1 (fused scan+prep): 256 blocks x 1024 threads, 32 rows/block.
// Distributed scan; all blocks co-resident (launch_bounds 1024,2).
// ---------------------------------------------------------------------------
__global__ __launch_bounds__(1024, 2) void prep_kernel(const float* __restrict__ qemb,
                                                       const float* __restrict__ kemb,
                                                       const uint8_t* __restrict__ maskraw) {
    __shared__ int s_nz;
    __shared__ unsigned s_bits;
    __shared__ int s_base, s_total;
    int tid = threadIdx.x, lane = tid & 31, warp = tid >> 5;
    int bid = blockIdx.x;
    int br0 = bid * 32;

    if (tid == 0) s_nz = 0;
    if (bid == 0 && tid == 512) g_done2 = 0;   // reset gemm counter this replay
    __syncthreads();

    // --- dtype sniff: one uint2 load/thread over the byte region ---
    const uint2* mv = (const uint2*)maskraw;
    uint2 v = mv[tid];
    int local = nz4(v.x) | nz4(v.y);
    if (tid == 1023) {                         // tail bytes 8192..8199
        uint2 t = mv[1024];
        local |= nz4(t.x) | nz4(t.y);
    }
#pragma unroll
    for (int o = 16; o; o >>= 1) local |= __shfl_xor_sync(0xffffffffu, local, o);
    if (lane == 0 && local) atomicOr(&s_nz, local);
    __syncthreads();

    int nz = s_nz;
    int mode;                       // 0=uint8, 1=int32, 2=float32
    if ((nz & 0xE) == 0)       mode = 1;
    else if ((nz & 0x3) == 0)  mode = 2;
    else                       mode = 0;

    // --- phase A: this block's 32 valid flags (warp 0), publish count ---
    if (warp == 0) {
        int row = br0 + lane;
        int b = row >> 10, r = row & 1023;
        int mi = b * Nn + r + 1;
        int vv;
        if (mode == 1)      vv = ((const int*)maskraw)[mi] != 0;
        else if (mode == 2) vv = ((const float*)maskraw)[mi] != 0.0f;
        else                vv = maskraw[mi] != 0;
        unsigned bits = __ballot_sync(0xffffffffu, vv);
        if (lane == 0) {
            s_bits = bits;
            g_blkcnt[bid] = __popc(bits);
            __threadfence();
            atomicAdd(&g_arr, 1);
        }
    }

    // --- wait for all 256 block counts (short: phase A is parallel) ---
    if (tid == 0) {
        while (atomicAdd(&g_arr, 0) < NBLKP) __nanosleep(32);
    }
    __syncthreads();
    __threadfence();

    // --- exclusive base + total over 256 counts (warp 0) ---
    if (warp == 0) {
        int t = 0, s = 0;
#pragma unroll
        for (int j = 0; j < 8; j++) {
            int idx = lane * 8 + j;
            int cc = g_blkcnt[idx];
            t += cc;
            if (idx < bid) s += cc;
        }
#pragma unroll
        for (int o = 16; o; o >>= 1) {
            t += __shfl_xor_sync(0xffffffffu, t, o);
            s += __shfl_xor_sync(0xffffffffu, s, o);
        }
        if (lane == 0) { s_base = s; s_total = t; }
    }
    __syncthreads();

    if (bid == 0 && tid == 0) g_count = s_total;

    // --- phase B: gather. one warp per row ---
    unsigned bits = s_bits;
    if (!((bits >> warp) & 1u)) return;
    int pos = s_base + __popc(bits & ((1u << warp) - 1u));
    int row = br0 + warp;
    int b = row >> 10, r = row & 1023;
    float2 qv = ((const float2*)(qemb + (size_t)(b * Nn + r) * Dd))[lane];
    float2 kv = ((const float2*)(kemb + (size_t)(b * Nn + r + 1) * Dd))[lane];
    float qs = fmaf(qv.x, qv.x, qv.y * qv.y);
    float ks = fmaf(kv.x, kv.x, kv.y * kv.y);
#pragma unroll
    for (int o = 16; o; o >>= 1) {
        qs += __shfl_xor_sync(0xffffffffu, qs, o);
        ks += __shfl_xor_sync(0xffffffffu, ks, o);
    }
    float qn = SCALE_Q / fmaxf(sqrtf(qs), 1e-12f);
    float kn = 1.0f    / fmaxf(sqrtf(ks), 1e-12f);
    __nv_bfloat162 qb = __floats2bfloat162_rn(qv.x * qn, qv.y * qn);
    __nv_bfloat162 kb = __floats2bfloat162_rn(kv.x * kn, kv.y * kn);
    ((__nv_bfloat162*)(g_qh + (size_t)pos * Dd))[lane] = qb;
    ((__nv_bfloat162*)(g_kh + (size_t)pos * Dd))[lane] = kb;
    float d = fmaf(__bfloat162float(qb.x), __bfloat162float(kb.x),
                   __bfloat162float(qb.y) * __bfloat162float(kb.y));
#pragma unroll
    for (int o = 16; o; o >>= 1) d += __shfl_xor_sync(0xffffffffu, d, o);
    if (lane == 0) g_diag[pos] = d;
}

// ---------------------------------------------------------------------------
// Kernel 2: 128x128 bf16 tensor-core GEMM + fused exp2 (f32 MUFU) row-sum.
// grid = 512 blocks, launch_bounds(256,3) -> 24 warps/SM. A fragments are
// re-ldsm'd per k-step (no hoist) to fit the 85-reg budget for 3 CTAs/SM.
// SPLITS=16: each item covers ntiles/16 column tiles (2 at count~4096).
// cp.async double-buffered B pipeline; last-arriving block does final reduce.
// ---------------------------------------------------------------------------
__global__ __launch_bounds__(256, 3) void gemm_kernel(float* __restrict__ out) {
    __shared__ __align__(16) uint4 As[BM * 8];      // 16 KB
    __shared__ __align__(16) uint4 Bs[2][BN * 8];   // 32 KB double buffer

    float* ssum    = (float*)As;                    // [2][BM] overlay (post-loop)
    int*   amLastp = (int*)((char*)As + 1024);
    float* sblk    = (float*)((char*)As + 1088);    // 8 floats

    int count = g_count;
    int tid   = threadIdx.x;
    int lane  = tid & 31;
    int wid   = tid >> 5;
    int wm    = wid & 3;      // 0..3 : rows wm*32
    int wn    = wid >> 2;     // 0..1 : cols wn*64

    uint32_t asb = (uint32_t)__cvta_generic_to_shared(As);
    uint32_t bsb = (uint32_t)__cvta_generic_to_shared(Bs);
    int ntiles = (count + BN - 1) >> 7;
    int nitems = ntiles * SPLITS;

    for (int item = blockIdx.x; item < nitems; item += NBLK_B) {
        int row0  = (item >> 4) * BM;
        int split = item & 15;
        if (row0 >= count) continue;

        // issue A tile (cp.async, swizzled)
        {
            const char* src = (const char*)(g_qh + (size_t)row0 * Dd);
#pragma unroll
            for (int i = 0; i < 4; i++) {
                int c = tid + i * 256;
                int r = c >> 3, k16 = c & 7;
                cpa16(asb + (uint32_t)((r * 8 + (k16 ^ (r & 7))) * 16), src + (size_t)c * 16);
            }
        }
        cpa_commit();                       // group: A
        // first B tile into buf 0 (if any tile exists for this split)
        if (split < ntiles) {
            const char* src = (const char*)(g_kh + ((size_t)split << 7) * Dd);
#pragma unroll
            for (int i = 0; i < 4; i++) {
                int c = tid + i * 256;
                int r = c >> 3, k16 = c & 7;
                cpa16(bsb + (uint32_t)((r * 8 + (k16 ^ (r & 7))) * 16), src + (size_t)c * 16);
            }
        }
        cpa_commit();                       // group: B0
        cpa_wait<1>();                      // A retired (B0 may be in flight)
        __syncthreads();

        float rsum[4] = {0.f, 0.f, 0.f, 0.f};
        int ct = split, buf = 0;

        while (ct < ntiles) {
            cpa_wait<0>();                  // B(ct) resident in Bs[buf]
            __syncthreads();
            int ctn = ct + SPLITS;
            if (ctn < ntiles) {             // prefetch next into other buffer
                const char* src = (const char*)(g_kh + ((size_t)ctn << 7) * Dd);
                uint32_t base = bsb + (buf ^ 1) * 16384;
#pragma unroll
                for (int i = 0; i < 4; i++) {
                    int c = tid + i * 256;
                    int r = c >> 3, k16 = c & 7;
                    cpa16(base + (uint32_t)((r * 8 + (k16 ^ (r & 7))) * 16), src + (size_t)c * 16);
                }
            }
            cpa_commit();

            int col0 = ct << 7;
            bool full = (col0 + BN) <= count;
            uint32_t bb = bsb + buf * 16384;

#pragma unroll
            for (int nh = 0; nh < 2; nh++) {
                float acc[2][4][4];
#pragma unroll
                for (int mi = 0; mi < 2; mi++)
#pragma unroll
                    for (int ni = 0; ni < 4; ni++)
#pragma unroll
                        for (int j = 0; j < 4; j++) acc[mi][ni][j] = C0x;

#pragma unroll
                for (int ks = 0; ks < 4; ks++) {
                    // A fragments re-loaded per k-step (keeps regs <= 85)
                    uint32_t afr[2][4];
#pragma unroll
                    for (int mi = 0; mi < 2; mi++) {
                        int m = lane >> 3;
                        int r = wm * 32 + mi * 16 + ((m & 1) << 3) + (lane & 7);
                        int c = 2 * ks + (m >> 1);
                        ldsm4(afr[mi], asb + (uint32_t)(r * 8 + (c ^ (r & 7))) * 16);
                    }
                    uint32_t bfr[2][4];
#pragma unroll
                    for (int p = 0; p < 2; p++) {
                        int ni0 = nh * 4 + p * 2;
                        int m = lane >> 3;
                        int r = wn * 64 + ni0 * 8 + ((m >> 1) << 3) + (lane & 7);
                        int c = 2 * ks + (m & 1);
                        ldsm4(bfr[p], bb + (uint32_t)(r * 8 + (c ^ (r & 7))) * 16);
                    }
#pragma unroll
                    for (int mi = 0; mi < 2; mi++) {
                        mma16816(acc[mi][0], afr[mi], bfr[0][0], bfr[0][1]);
                        mma16816(acc[mi][1], afr[mi], bfr[0][2], bfr[0][3]);
                        mma16816(acc[mi][2], afr[mi], bfr[1][0], bfr[1][1]);
                        mma16816(acc[mi][3], afr[mi], bfr[1][2], bfr[1][3]);
                    }
                }

                if (full) {
#pragma unroll
                    for (int mi = 0; mi < 2; mi++)
#pragma unroll
                        for (int ni = 0; ni < 4; ni++) {
                            rsum[mi * 2 + 0] += ex2(acc[mi][ni][0]) + ex2(acc[mi][ni][1]);
                            rsum[mi * 2 + 1] += ex2(acc[mi][ni][2]) + ex2(acc[mi][ni][3]);
                        }
                } else {
                    int cb = col0 + wn * 64 + nh * 32 + (lane & 3) * 2;
#pragma unroll
                    for (int mi = 0; mi < 2; mi++)
#pragma unroll
                        for (int ni = 0; ni < 4; ni++) {
                            int c0 = cb + ni * 8;
                            float e0 = (c0     < count) ? ex2(acc[mi][ni][0]) : 0.f;
                            float e1 = (c0 + 1 < count) ? ex2(acc[mi][ni][1]) : 0.f;
                            float e2 = (c0     < count) ? ex2(acc[mi][ni][2]) : 0.f;
                            float e3 = (c0 + 1 < count) ? ex2(acc[mi][ni][3]) : 0.f;
                            rsum[mi * 2 + 0] += e0 + e1;
                            rsum[mi * 2 + 1] += e2 + e3;
                        }
                }
            }
            ct = ctn; buf ^= 1;
        }

        // lanes sharing a row: l%4 (column quads)
#pragma unroll
        for (int i = 0; i < 4; i++) {
            rsum[i] += __shfl_xor_sync(0xffffffffu, rsum[i], 1);
            rsum[i] += __shfl_xor_sync(0xffffffffu, rsum[i], 2);
        }
        __syncthreads();                 // all warps done reading As -> overlay
        if ((lane & 3) == 0) {
#pragma unroll
            for (int i = 0; i < 4; i++) {
                int row = wm * 32 + (i >> 1) * 16 + (i & 1) * 8 + (lane >> 2);
                ssum[wn * BM + row] = rsum[i];
            }
        }
        __syncthreads();
        // write even when this split had zero tiles (rsum=0) -> replay-safe
        if (tid < BM)
            g_S2[(size_t)(row0 + tid) * SPLITS + split] = ssum[tid] + ssum[BM + tid];
        __syncthreads();                 // ssum consumed before next item's A load
    }

    // ---- fused final reduce: last-arriving block does it all ----
    __threadfence();            // order this thread's global stores
    __syncthreads();            // all threads' fences done before tid0 arrives
    if (tid == 0)
        *amLastp = (atomicAdd(&g_done2, 1) == NBLK_B - 1) ? 1 : 0;
    __syncthreads();
    if (!*amLastp) return;
    __threadfence();            // acquire: make all blocks' stores visible

    if (tid == 0) g_arr = 0;    // reset prep arrival counter for next replay

    float acc = 0.f;
    for (int r = tid; r < count; r += 256) {
        const float4* p = (const float4*)&g_S2[(size_t)r * SPLITS];
        float4 a = p[0], b = p[1], c = p[2], d = p[3];
        float S = (((a.x + a.y) + (a.z + a.w)) + ((b.x + b.y) + (b.z + b.w)))
                + (((c.x + c.y) + (c.z + c.w)) + ((d.x + d.y) + (d.z + d.w)));
        acc += g_diag[r] + C0x - lg2(S);
    }
#pragma unroll
    for (int o = 16; o; o >>= 1) acc += __shfl_xor_sync(0xffffffffu, acc, o);
    if (lane == 0) sblk[wid] = acc;
    __syncthreads();
    if (tid == 0) {
        float s = 0.f;
#pragma unroll
        for (int w = 0; w < 8; w++) s += sblk[w];
        out[0] = -LN2f * s / (float)count;
    }
}

// ---------------------------------------------------------------------------
extern "C" void kernel_launch(void* const* d_in, const int* in_sizes, int n_in,
                              void* d_out, int out_size) {
    const float*   q = (const float*)d_in[0];
    const float*   k = (const float*)d_in[1];
    const uint8_t* m = (const uint8_t*)d_in[2];
    (void)in_sizes; (void)n_in; (void)out_size;

    prep_kernel<<<NBLKP, 1024>>>(q, k, m);
    gemm_kernel<<<NBLK_B, 256>>>((float*)d_out);
}

// round 17
// speedup vs baseline: 1.0220x; 1.0129x over previous
#include <cuda_runtime.h>
#include <cuda_bf16.h>
#include <stdint.h>
#include <math.h>

// Problem constants (B=8, N=1025, D=64)
#define Nn     1025
#define Dd     64
#define Tt     8192      // B*(N-1)
#define MASKN  8200      // B*N

#define BM     128
#define BN     128
#define SPLITS 8
#define NBLK_B 256                  // gemm grid; item loop covers (rowtile,split)
#define NBLKP  256                  // prep blocks (32 rows each)

#define SCALE_Q 28.85390081777927f   // log2(e)/0.05
#define C0x    (-28.85390081777927f) // -20*log2(e)
#define LN2f    0.6931471805599453f

// Device scratch (zero-initialized at module load; rows >= count stay 0)
__device__ int   g_count;
__device__ int   g_arr;     // prep arrival counter; reset by gemm each replay
__device__ int   g_done2;   // gemm arrival counter; reset by prep each replay
__device__ int   g_blkcnt[NBLKP];
__device__ __align__(16) __nv_bfloat16 g_qh[Tt * Dd];
__device__ __align__(16) __nv_bfloat16 g_kh[Tt * Dd];
__device__ float g_diag[Tt];
__device__ __align__(32) float g_S2[Tt * SPLITS];   // [row][split]

// ---------------------------------------------------------------------------
// PTX helpers
// ---------------------------------------------------------------------------
__device__ __forceinline__ float ex2(float x) {
    float r; asm("ex2.approx.f32 %0, %1;" : "=f"(r) : "f"(x)); return r;
}
__device__ __forceinline__ float lg2(float x) {
    float r; asm("lg2.approx.f32 %0, %1;" : "=f"(r) : "f"(x)); return r;
}
__device__ __forceinline__ void ldsm4(uint32_t r[4], uint32_t addr) {
    asm volatile("ldmatrix.sync.aligned.m8n8.x4.shared.b16 {%0,%1,%2,%3}, [%4];"
        : "=r"(r[0]), "=r"(r[1]), "=r"(r[2]), "=r"(r[3]) : "r"(addr));
}
__device__ __forceinline__ void mma16816(float d[4], const uint32_t a[4],
                                         uint32_t b0, uint32_t b1) {
    asm volatile(
        "mma.sync.aligned.m16n8k16.row.col.f32.bf16.bf16.f32 "
        "{%0,%1,%2,%3},{%4,%5,%6,%7},{%8,%9},{%0,%1,%2,%3};"
        : "+f"(d[0]), "+f"(d[1]), "+f"(d[2]), "+f"(d[3])
        : "r"(a[0]), "r"(a[1]), "r"(a[2]), "r"(a[3]), "r"(b0), "r"(b1));
}
__device__ __forceinline__ void cpa16(uint32_t dst, const void* src) {
    asm volatile("cp.async.cg.shared.global [%0], [%1], 16;" :: "r"(dst), "l"(src));
}
__device__ __forceinline__ void cpa_commit() {
    asm volatile("cp.async.commit_group;" ::: "memory");
}
template<int N> __device__ __forceinline__ void cpa_wait() {
    asm volatile("cp.async.wait_group %0;" :: "n"(N) : "memory");
}

// nz-pattern contribution of 4 bytes: byte j -> bit j
__device__ __forceinline__ int nz4(uint32_t w) {
    int p = 0;
    if (w & 0x000000FFu) p |= 1;
    if (w & 0x0000FF00u) p |= 2;
    if (w & 0x00FF0000u) p |= 4;
    if (w & 0xFF000000u) p |= 8;
    return p;
}

// ---------------------------------------------------------------------------
// Kernel 1 (fused scan+prep): 256 blocks x 1024 threads, 32 rows/block.
// q/k loads + normalization issued BEFORE the global arrival spin so memory
// latency is hidden under the distributed-scan synchronization.
// ---------------------------------------------------------------------------
__global__ __launch_bounds__(1024, 2) void prep_kernel(const float* __restrict__ qemb,
                                                       const float* __restrict__ kemb,
                                                       const uint8_t* __restrict__ maskraw) {
    __shared__ int s_nz;
    __shared__ unsigned s_bits;
    __shared__ int s_base, s_total;
    int tid = threadIdx.x, lane = tid & 31, warp = tid >> 5;
    int bid = blockIdx.x;
    int br0 = bid * 32;

    if (tid == 0) s_nz = 0;
    if (bid == 0 && tid == 512) g_done2 = 0;   // reset gemm counter this replay
    __syncthreads();

    // --- issue q/k row loads first (mask-independent; one warp per row) ---
    int row = br0 + warp;
    int rb = row >> 10, rr = row & 1023;
    float2 qv = ((const float2*)(qemb + (size_t)(rb * Nn + rr) * Dd))[lane];
    float2 kv = ((const float2*)(kemb + (size_t)(rb * Nn + rr + 1) * Dd))[lane];

    // --- dtype sniff: one uint2 load/thread over the byte region ---
    const uint2* mv = (const uint2*)maskraw;
    uint2 v = mv[tid];
    int local = nz4(v.x) | nz4(v.y);
    if (tid == 1023) {                         // tail bytes 8192..8199
        uint2 t = mv[1024];
        local |= nz4(t.x) | nz4(t.y);
    }
#pragma unroll
    for (int o = 16; o; o >>= 1) local |= __shfl_xor_sync(0xffffffffu, local, o);
    if (lane == 0 && local) atomicOr(&s_nz, local);
    __syncthreads();

    int nz = s_nz;
    int mode;                       // 0=uint8, 1=int32, 2=float32
    if ((nz & 0xE) == 0)       mode = 1;
    else if ((nz & 0x3) == 0)  mode = 2;
    else                       mode = 0;

    // --- phase A: this block's 32 valid flags (warp 0), publish count ---
    if (warp == 0) {
        int trow = br0 + lane;
        int b = trow >> 10, r = trow & 1023;
        int mi = b * Nn + r + 1;
        int vv;
        if (mode == 1)      vv = ((const int*)maskraw)[mi] != 0;
        else if (mode == 2) vv = ((const float*)maskraw)[mi] != 0.0f;
        else                vv = maskraw[mi] != 0;
        unsigned bits = __ballot_sync(0xffffffffu, vv);
        if (lane == 0) {
            s_bits = bits;
            g_blkcnt[bid] = __popc(bits);
            __threadfence();
            atomicAdd(&g_arr, 1);
        }
    }

    // --- mask-independent normalization while other blocks publish ---
    float qs = fmaf(qv.x, qv.x, qv.y * qv.y);
    float ks = fmaf(kv.x, kv.x, kv.y * kv.y);
#pragma unroll
    for (int o = 16; o; o >>= 1) {
        qs += __shfl_xor_sync(0xffffffffu, qs, o);
        ks += __shfl_xor_sync(0xffffffffu, ks, o);
    }
    float qn = SCALE_Q / fmaxf(sqrtf(qs), 1e-12f);
    float kn = 1.0f    / fmaxf(sqrtf(ks), 1e-12f);
    __nv_bfloat162 qb = __floats2bfloat162_rn(qv.x * qn, qv.y * qn);
    __nv_bfloat162 kb = __floats2bfloat162_rn(kv.x * kn, kv.y * kn);
    float d = fmaf(__bfloat162float(qb.x), __bfloat162float(kb.x),
                   __bfloat162float(qb.y) * __bfloat162float(kb.y));
#pragma unroll
    for (int o = 16; o; o >>= 1) d += __shfl_xor_sync(0xffffffffu, d, o);

    // --- wait for all 256 block counts ---
    if (tid == 0) {
        while (atomicAdd(&g_arr, 0) < NBLKP) __nanosleep(32);
    }
    __syncthreads();
    __threadfence();

    // --- exclusive base + total over 256 counts (warp 0) ---
    if (warp == 0) {
        int t = 0, s = 0;
#pragma unroll
        for (int j = 0; j < 8; j++) {
            int idx = lane * 8 + j;
            int cc = g_blkcnt[idx];
            t += cc;
            if (idx < bid) s += cc;
        }
#pragma unroll
        for (int o = 16; o; o >>= 1) {
            t += __shfl_xor_sync(0xffffffffu, t, o);
            s += __shfl_xor_sync(0xffffffffu, s, o);
        }
        if (lane == 0) { s_base = s; s_total = t; }
    }
    __syncthreads();

    if (bid == 0 && tid == 0) g_count = s_total;

    // --- compact stores (valid rows only) ---
    unsigned bits = s_bits;
    if (!((bits >> warp) & 1u)) return;
    int pos = s_base + __popc(bits & ((1u << warp) - 1u));
    ((__nv_bfloat162*)(g_qh + (size_t)pos * Dd))[lane] = qb;
    ((__nv_bfloat162*)(g_kh + (size_t)pos * Dd))[lane] = kb;
    if (lane == 0) g_diag[pos] = d;
}

// ---------------------------------------------------------------------------
// Kernel 2: 128x128 bf16 tensor-core GEMM + fused exp2 (f32 MUFU) row-sum.
// grid = 256 blocks; items (row-tile, split) looped -> no dead blocks.
// A fragments hoisted per item; B ldsm offsets precomputed (nh=1 = +4096).
// cp.async double-buffered B pipeline; last-arriving block does final reduce.
// ---------------------------------------------------------------------------
__global__ __launch_bounds__(256, 2) void gemm_kernel(float* __restrict__ out) {
    __shared__ __align__(16) uint4 As[BM * 8];      // 16 KB (reused post-afrag)
    __shared__ __align__(16) uint4 Bs[2][BN * 8];   // 32 KB double buffer

    float* ssum    = (float*)As;                    // [2][BM] = 1 KB overlay
    int*   amLastp = (int*)((char*)As + 1024);
    float* sblk    = (float*)((char*)As + 1088);    // 8 floats

    int count = g_count;
    int tid   = threadIdx.x;
    int lane  = tid & 31;
    int wid   = tid >> 5;
    int wm    = wid & 3;      // 0..3 : rows wm*32
    int wn    = wid >> 2;     // 0..1 : cols wn*64

    uint32_t asb = (uint32_t)__cvta_generic_to_shared(As);
    uint32_t bsb = (uint32_t)__cvta_generic_to_shared(Bs);
    int ntiles = (count + BN - 1) >> 7;
    int nitems = ntiles * SPLITS;

    // precompute B ldsm offsets (nh=0); nh=1 adds +4096 (r+32 in swizzled SW128)
    uint32_t offB[2][4];
    {
        int m = lane >> 3;
#pragma unroll
        for (int p = 0; p < 2; p++)
#pragma unroll
            for (int ks = 0; ks < 4; ks++) {
                int r = wn * 64 + p * 16 + ((m >> 1) << 3) + (lane & 7);
                int c = 2 * ks + (m & 1);
                offB[p][ks] = (uint32_t)(r * 8 + (c ^ (r & 7))) * 16;
            }
    }

    for (int item = blockIdx.x; item < nitems; item += NBLK_B) {
        int row0  = (item >> 3) * BM;
        int split = item & 7;
        if (row0 >= count) continue;

        // issue A tile (cp.async, swizzled)
        {
            const char* src = (const char*)(g_qh + (size_t)row0 * Dd);
#pragma unroll
            for (int i = 0; i < 4; i++) {
                int c = tid + i * 256;
                int r = c >> 3, k16 = c & 7;
                cpa16(asb + (uint32_t)((r * 8 + (k16 ^ (r & 7))) * 16), src + (size_t)c * 16);
            }
        }
        cpa_commit();                       // group: A
        // first B tile into buf 0
        if (split < ntiles) {
            const char* src = (const char*)(g_kh + ((size_t)split << 7) * Dd);
#pragma unroll
            for (int i = 0; i < 4; i++) {
                int c = tid + i * 256;
                int r = c >> 3, k16 = c & 7;
                cpa16(bsb + (uint32_t)((r * 8 + (k16 ^ (r & 7))) * 16), src + (size_t)c * 16);
            }
        }
        cpa_commit();                       // group: B0
        cpa_wait<1>();                      // A retired (B0 may be in flight)
        __syncthreads();

        // Hoist all A fragments (rows wm*32..+32, full K=64)
        uint32_t afrag[2][4][4];
#pragma unroll
        for (int mi = 0; mi < 2; mi++)
#pragma unroll
            for (int ks = 0; ks < 4; ks++) {
                int m = lane >> 3;
                int r = wm * 32 + mi * 16 + ((m & 1) << 3) + (lane & 7);
                int c = 2 * ks + (m >> 1);
                ldsm4(afrag[mi][ks], asb + (uint32_t)(r * 8 + (c ^ (r & 7))) * 16);
            }
        __syncthreads();                    // As dead -> overlay safe

        float rsum[4] = {0.f, 0.f, 0.f, 0.f};
        int ct = split, buf = 0;

        while (ct < ntiles) {
            cpa_wait<0>();                  // B(ct) resident in Bs[buf]
            __syncthreads();
            int ctn = ct + SPLITS;
            if (ctn < ntiles) {             // prefetch next into other buffer
                const char* src = (const char*)(g_kh + ((size_t)ctn << 7) * Dd);
                uint32_t base = bsb + (buf ^ 1) * 16384;
#pragma unroll
                for (int i = 0; i < 4; i++) {
                    int c = tid + i * 256;
                    int r = c >> 3, k16 = c & 7;
                    cpa16(base + (uint32_t)((r * 8 + (k16 ^ (r & 7))) * 16), src + (size_t)c * 16);
                }
            }
            cpa_commit();

            int col0 = ct << 7;
            bool full = (col0 + BN) <= count;
            uint32_t bb = bsb + buf * 16384;

#pragma unroll
            for (int nh = 0; nh < 2; nh++) {
                uint32_t bnh = bb + nh * 4096;
                float acc[2][4][4];
#pragma unroll
                for (int mi = 0; mi < 2; mi++)
#pragma unroll
                    for (int ni = 0; ni < 4; ni++)
#pragma unroll
                        for (int j = 0; j < 4; j++) acc[mi][ni][j] = C0x;

#pragma unroll
                for (int ks = 0; ks < 4; ks++) {
                    uint32_t bfr[2][4];
                    ldsm4(bfr[0], bnh + offB[0][ks]);
                    ldsm4(bfr[1], bnh + offB[1][ks]);
#pragma unroll
                    for (int mi = 0; mi < 2; mi++) {
                        mma16816(acc[mi][0], afrag[mi][ks], bfr[0][0], bfr[0][1]);
                        mma16816(acc[mi][1], afrag[mi][ks], bfr[0][2], bfr[0][3]);
                        mma16816(acc[mi][2], afrag[mi][ks], bfr[1][0], bfr[1][1]);
                        mma16816(acc[mi][3], afrag[mi][ks], bfr[1][2], bfr[1][3]);
                    }
                }

                if (full) {
#pragma unroll
                    for (int mi = 0; mi < 2; mi++)
#pragma unroll
                        for (int ni = 0; ni < 4; ni++) {
                            rsum[mi * 2 + 0] += ex2(acc[mi][ni][0]) + ex2(acc[mi][ni][1]);
                            rsum[mi * 2 + 1] += ex2(acc[mi][ni][2]) + ex2(acc[mi][ni][3]);
                        }
                } else {
                    int cb = col0 + wn * 64 + nh * 32 + (lane & 3) * 2;
#pragma unroll
                    for (int mi = 0; mi < 2; mi++)
#pragma unroll
                        for (int ni = 0; ni < 4; ni++) {
                            int c0 = cb + ni * 8;
                            float e0 = (c0     < count) ? ex2(acc[mi][ni][0]) : 0.f;
                            float e1 = (c0 + 1 < count) ? ex2(acc[mi][ni][1]) : 0.f;
                            float e2 = (c0     < count) ? ex2(acc[mi][ni][2]) : 0.f;
                            float e3 = (c0 + 1 < count) ? ex2(acc[mi][ni][3]) : 0.f;
                            rsum[mi * 2 + 0] += e0 + e1;
                            rsum[mi * 2 + 1] += e2 + e3;
                        }
                }
            }
            ct = ctn; buf ^= 1;
        }

        // lanes sharing a row: l%4 (column quads)
#pragma unroll
        for (int i = 0; i < 4; i++) {
            rsum[i] += __shfl_xor_sync(0xffffffffu, rsum[i], 1);
            rsum[i] += __shfl_xor_sync(0xffffffffu, rsum[i], 2);
        }
        __syncthreads();                 // overlay region free
        if ((lane & 3) == 0) {
#pragma unroll
            for (int i = 0; i < 4; i++) {
                int row = wm * 32 + (i >> 1) * 16 + (i & 1) * 8 + (lane >> 2);
                ssum[wn * BM + row] = rsum[i];
            }
        }
        __syncthreads();
        if (tid < BM)
            g_S2[(size_t)(row0 + tid) * SPLITS + split] = ssum[tid] + ssum[BM + tid];
        __syncthreads();                 // ssum consumed before next item's A load
    }

    // ---- fused final reduce: last-arriving block does it all ----
    __threadfence();            // order this thread's global stores
    __syncthreads();            // all threads' fences done before tid0 arrives
    if (tid == 0)
        *amLastp = (atomicAdd(&g_done2, 1) == NBLK_B - 1) ? 1 : 0;
    __syncthreads();
    if (!*amLastp) return;
    __threadfence();            // acquire: make all blocks' stores visible

    if (tid == 0) g_arr = 0;    // reset prep arrival counter for next replay

    float acc = 0.f;
    for (int r = tid; r < count; r += 256) {
        float4 a = *(const float4*)&g_S2[(size_t)r * SPLITS];
        float4 b = *(const float4*)&g_S2[(size_t)r * SPLITS + 4];
        float S = ((a.x + a.y) + (a.z + a.w)) + ((b.x + b.y) + (b.z + b.w));
        acc += g_diag[r] + C0x - lg2(S);
    }
#pragma unroll
    for (int o = 16; o; o >>= 1) acc += __shfl_xor_sync(0xffffffffu, acc, o);
    if (lane == 0) sblk[wid] = acc;
    __syncthreads();
    if (tid == 0) {
        float s = 0.f;
#pragma unroll
        for (int w = 0; w < 8; w++) s += sblk[w];
        out[0] = -LN2f * s / (float)count;
    }
}

// ---------------------------------------------------------------------------
extern "C" void kernel_launch(void* const* d_in, const int* in_sizes, int n_in,
                              void* d_out, int out_size) {
    const float*   q = (const float*)d_in[0];
    const float*   k = (const float*)d_in[1];
    const uint8_t* m = (const uint8_t*)d_in[2];
    (void)in_sizes; (void)n_in; (void)out_size;

    prep_kernel<<<NBLKP, 1024>>>(q, k, m);
    gemm_kernel<<<NBLK_B, 256>>>((float*)d_out);
}